// round 2
// baseline (speedup 1.0000x reference)
#include <cuda_runtime.h>
#include <cuda_bf16.h>

// Problem constants
#define Bn   4
#define Cc   256
#define Hh   64
#define Ww   64
#define HW   4096           // Hh*Ww
#define NP   16384          // Bn*HW pixels
#define EPSV 1e-5f
#define QSCALE 0.0625f      // C^-0.5 = 1/16

// Scratch (static __device__; no allocations allowed)
__device__ float g_xn [NP * Cc];   // normalized, NHWC
__device__ float g_q  [NP * Cc];
__device__ float g_k  [NP * Cc];
__device__ float g_v  [NP * Cc];
__device__ float g_ctx[NP * Cc];
__device__ float g_on [NP * Cc];   // out NHWC before final transpose
__device__ float g_mean[Bn * Cc];
__device__ float g_rstd[Bn * Cc];

// ---------------------------------------------------------------------------
// Kernel 1: per-(b,c)-plane mean / rstd over H*W
// ---------------------------------------------------------------------------
__global__ void ln_stats_kernel(const float* __restrict__ x) {
    int plane = blockIdx.x;                       // b*Cc + c
    const float* p = x + (size_t)plane * HW;
    float s = 0.f, ss = 0.f;
    for (int i = threadIdx.x; i < HW; i += 256) {
        float v = p[i];
        s += v; ss += v * v;
    }
    #pragma unroll
    for (int o = 16; o; o >>= 1) {
        s  += __shfl_xor_sync(0xffffffffu, s,  o);
        ss += __shfl_xor_sync(0xffffffffu, ss, o);
    }
    __shared__ float sh1[8], sh2[8];
    int wid = threadIdx.x >> 5, ln = threadIdx.x & 31;
    if (ln == 0) { sh1[wid] = s; sh2[wid] = ss; }
    __syncthreads();
    if (threadIdx.x < 8) {
        s = sh1[threadIdx.x]; ss = sh2[threadIdx.x];
        #pragma unroll
        for (int o = 4; o; o >>= 1) {
            s  += __shfl_xor_sync(0xffu, s,  o);
            ss += __shfl_xor_sync(0xffu, ss, o);
        }
        if (threadIdx.x == 0) {
            float mu  = s * (1.0f / HW);
            float var = ss * (1.0f / HW) - mu * mu;
            g_mean[plane] = mu;
            g_rstd[plane] = rsqrtf(var + EPSV);
        }
    }
}

// ---------------------------------------------------------------------------
// Kernel 2: normalize + transpose NCHW -> NHWC (32x32 smem tile)
// grid (HW/32, Cc/32, Bn), block (32,32)
// ---------------------------------------------------------------------------
__global__ void ln_norm_t_kernel(const float* __restrict__ x) {
    __shared__ float t[32][33];
    int b   = blockIdx.z;
    int c0  = blockIdx.y * 32;
    int hw0 = blockIdx.x * 32;
    int c  = c0  + threadIdx.y;
    int hw = hw0 + threadIdx.x;
    int plane = b * Cc + c;
    float v = x[(size_t)plane * HW + hw];
    v = (v - g_mean[plane]) * g_rstd[plane];
    t[threadIdx.y][threadIdx.x] = v;
    __syncthreads();
    g_xn[((size_t)(b * HW + hw0 + threadIdx.y)) * Cc + c0 + threadIdx.x] =
        t[threadIdx.x][threadIdx.y];
}

// ---------------------------------------------------------------------------
// Shared GEMM tile core: C[128x128] += A[128x256] * W[128x256]^T
// 256 threads, 8x8 accumulators/thread, BK=16
// ---------------------------------------------------------------------------
__device__ __forceinline__ void gemm_tile_128(
    const float* __restrict__ A, const float* __restrict__ Wt,
    int m0, int n0, float acc[8][8])
{
    __shared__ float As[16][132];
    __shared__ float Bs[16][132];
    const int tid = threadIdx.x;
    const int tx = tid & 15, ty = tid >> 4;
    const int lr = tid >> 2;            // 0..63
    const int lc = (tid & 3) << 2;      // 0,4,8,12

    for (int k0 = 0; k0 < 256; k0 += 16) {
        float4 a0 = *(const float4*)(A  + (size_t)(m0 + lr)      * Cc + k0 + lc);
        float4 a1 = *(const float4*)(A  + (size_t)(m0 + lr + 64) * Cc + k0 + lc);
        float4 b0 = *(const float4*)(Wt + (size_t)(n0 + lr)      * Cc + k0 + lc);
        float4 b1 = *(const float4*)(Wt + (size_t)(n0 + lr + 64) * Cc + k0 + lc);
        __syncthreads();
        As[lc+0][lr] = a0.x; As[lc+1][lr] = a0.y; As[lc+2][lr] = a0.z; As[lc+3][lr] = a0.w;
        As[lc+0][lr+64] = a1.x; As[lc+1][lr+64] = a1.y; As[lc+2][lr+64] = a1.z; As[lc+3][lr+64] = a1.w;
        Bs[lc+0][lr] = b0.x; Bs[lc+1][lr] = b0.y; Bs[lc+2][lr] = b0.z; Bs[lc+3][lr] = b0.w;
        Bs[lc+0][lr+64] = b1.x; Bs[lc+1][lr+64] = b1.y; Bs[lc+2][lr+64] = b1.z; Bs[lc+3][lr+64] = b1.w;
        __syncthreads();
        #pragma unroll
        for (int kk = 0; kk < 16; kk++) {
            float4 av0 = *(const float4*)&As[kk][ty * 8];
            float4 av1 = *(const float4*)&As[kk][ty * 8 + 4];
            float4 bv0 = *(const float4*)&Bs[kk][tx * 8];
            float4 bv1 = *(const float4*)&Bs[kk][tx * 8 + 4];
            float a[8] = {av0.x, av0.y, av0.z, av0.w, av1.x, av1.y, av1.z, av1.w};
            float bb[8] = {bv0.x, bv0.y, bv0.z, bv0.w, bv1.x, bv1.y, bv1.z, bv1.w};
            #pragma unroll
            for (int i = 0; i < 8; i++)
                #pragma unroll
                for (int j = 0; j < 8; j++)
                    acc[i][j] = fmaf(a[i], bb[j], acc[i][j]);
        }
    }
}

// ---------------------------------------------------------------------------
// Kernel 3: fused QKV GEMM.  grid (NP/128, 6), 256 threads
// blockIdx.y: 0,1 -> Q cols [0,128),[128,256); 2,3 -> K; 4,5 -> V
// ---------------------------------------------------------------------------
__global__ void __launch_bounds__(256, 2) gemm_qkv_kernel(
    const float* __restrict__ Wq, const float* __restrict__ bq,
    const float* __restrict__ Wk, const float* __restrict__ bk,
    const float* __restrict__ Wv, const float* __restrict__ bv)
{
    const int m0  = blockIdx.x * 128;
    const int sel = blockIdx.y >> 1;
    const int nb  = (blockIdx.y & 1) * 128;
    const float* Wt   = (sel == 0) ? Wq : (sel == 1) ? Wk : Wv;
    const float* bias = (sel == 0) ? bq : (sel == 1) ? bk : bv;
    float* out        = (sel == 0) ? g_q : (sel == 1) ? g_k : g_v;
    const float scale = (sel == 0) ? QSCALE : 1.0f;

    float acc[8][8];
    #pragma unroll
    for (int i = 0; i < 8; i++)
        #pragma unroll
        for (int j = 0; j < 8; j++) acc[i][j] = 0.f;

    gemm_tile_128(g_xn, Wt, m0, nb, acc);

    const int tx = threadIdx.x & 15, ty = threadIdx.x >> 4;
    #pragma unroll
    for (int i = 0; i < 8; i++) {
        int m = m0 + ty * 8 + i;
        #pragma unroll
        for (int j4 = 0; j4 < 8; j4 += 4) {
            int n = nb + tx * 8 + j4;
            float4 v;
            v.x = (acc[i][j4+0] + bias[n+0]) * scale;
            v.y = (acc[i][j4+1] + bias[n+1]) * scale;
            v.z = (acc[i][j4+2] + bias[n+2]) * scale;
            v.w = (acc[i][j4+3] + bias[n+3]) * scale;
            *(float4*)(out + (size_t)m * Cc + n) = v;
        }
    }
}

// ---------------------------------------------------------------------------
// Kernel 4: 3x3 neighborhood attention. One warp per pixel, 8 warps/block.
// OOB neighbors: k = bk, v = bv (zero-pad + linear semantics)
// ---------------------------------------------------------------------------
__global__ void __launch_bounds__(256) attn_kernel(
    const float* __restrict__ bk, const float* __restrict__ bv)
{
    int warp = (blockIdx.x * blockDim.x + threadIdx.x) >> 5;
    int lane = threadIdx.x & 31;
    if (warp >= NP) return;
    int b  = warp >> 12;
    int hw = warp & 4095;
    int h = hw >> 6, w = hw & 63;
    int co = lane * 8;

    const float* qp = g_q + (size_t)warp * Cc;
    float4 q0 = *(const float4*)(qp + co);
    float4 q1 = *(const float4*)(qp + co + 4);

    float logits[9];
    #pragma unroll
    for (int n = 0; n < 9; n++) {
        int dh = n / 3 - 1, dw = n % 3 - 1;
        int hh = h + dh, ww = w + dw;
        bool ok = (hh >= 0) & (hh < Hh) & (ww >= 0) & (ww < Ww);
        const float* kp = ok ? (g_k + (size_t)((b << 12) + (hh << 6) + ww) * Cc) : bk;
        float4 k0 = *(const float4*)(kp + co);
        float4 k1 = *(const float4*)(kp + co + 4);
        float d = q0.x*k0.x + q0.y*k0.y + q0.z*k0.z + q0.w*k0.w
                + q1.x*k1.x + q1.y*k1.y + q1.z*k1.z + q1.w*k1.w;
        #pragma unroll
        for (int o = 16; o; o >>= 1) d += __shfl_xor_sync(0xffffffffu, d, o);
        logits[n] = d;
    }

    float mx = logits[0];
    #pragma unroll
    for (int n = 1; n < 9; n++) mx = fmaxf(mx, logits[n]);
    float e[9]; float sum = 0.f;
    #pragma unroll
    for (int n = 0; n < 9; n++) { e[n] = __expf(logits[n] - mx); sum += e[n]; }
    float inv = 1.0f / sum;

    float acc[8] = {0,0,0,0,0,0,0,0};
    #pragma unroll
    for (int n = 0; n < 9; n++) {
        int dh = n / 3 - 1, dw = n % 3 - 1;
        int hh = h + dh, ww = w + dw;
        bool ok = (hh >= 0) & (hh < Hh) & (ww >= 0) & (ww < Ww);
        const float* vp = ok ? (g_v + (size_t)((b << 12) + (hh << 6) + ww) * Cc) : bv;
        float a = e[n] * inv;
        float4 v0 = *(const float4*)(vp + co);
        float4 v1 = *(const float4*)(vp + co + 4);
        acc[0] = fmaf(a, v0.x, acc[0]); acc[1] = fmaf(a, v0.y, acc[1]);
        acc[2] = fmaf(a, v0.z, acc[2]); acc[3] = fmaf(a, v0.w, acc[3]);
        acc[4] = fmaf(a, v1.x, acc[4]); acc[5] = fmaf(a, v1.y, acc[5]);
        acc[6] = fmaf(a, v1.z, acc[6]); acc[7] = fmaf(a, v1.w, acc[7]);
    }
    float* cp = g_ctx + (size_t)warp * Cc + co;
    *(float4*)(cp)     = make_float4(acc[0], acc[1], acc[2], acc[3]);
    *(float4*)(cp + 4) = make_float4(acc[4], acc[5], acc[6], acc[7]);
}

// ---------------------------------------------------------------------------
// Kernel 5: output projection GEMM. grid (NP/128, 2), 256 threads
// ---------------------------------------------------------------------------
__global__ void __launch_bounds__(256, 2) gemm_o_kernel(
    const float* __restrict__ Wo, const float* __restrict__ bo)
{
    const int m0 = blockIdx.x * 128;
    const int nb = blockIdx.y * 128;

    float acc[8][8];
    #pragma unroll
    for (int i = 0; i < 8; i++)
        #pragma unroll
        for (int j = 0; j < 8; j++) acc[i][j] = 0.f;

    gemm_tile_128(g_ctx, Wo, m0, nb, acc);

    const int tx = threadIdx.x & 15, ty = threadIdx.x >> 4;
    #pragma unroll
    for (int i = 0; i < 8; i++) {
        int m = m0 + ty * 8 + i;
        #pragma unroll
        for (int j4 = 0; j4 < 8; j4 += 4) {
            int n = nb + tx * 8 + j4;
            float4 v;
            v.x = acc[i][j4+0] + bo[n+0];
            v.y = acc[i][j4+1] + bo[n+1];
            v.z = acc[i][j4+2] + bo[n+2];
            v.w = acc[i][j4+3] + bo[n+3];
            *(float4*)(g_on + (size_t)m * Cc + n) = v;
        }
    }
}

// ---------------------------------------------------------------------------
// Kernel 6: NHWC -> NCHW transpose of final output
// grid (Cc/32, HW/32, Bn), block (32,32)
// ---------------------------------------------------------------------------
__global__ void out_transpose_kernel(float* __restrict__ dst) {
    __shared__ float t[32][33];
    int b   = blockIdx.z;
    int hw0 = blockIdx.y * 32;
    int c0  = blockIdx.x * 32;
    t[threadIdx.y][threadIdx.x] =
        g_on[((size_t)(b * HW + hw0 + threadIdx.y)) * Cc + c0 + threadIdx.x];
    __syncthreads();
    dst[((size_t)(b * Cc + c0 + threadIdx.y)) * HW + hw0 + threadIdx.x] =
        t[threadIdx.x][threadIdx.y];
}

// ---------------------------------------------------------------------------
extern "C" void kernel_launch(void* const* d_in, const int* in_sizes, int n_in,
                              void* d_out, int out_size) {
    const float* x  = (const float*)d_in[0];
    const float* Wq = (const float*)d_in[1];
    const float* bq = (const float*)d_in[2];
    const float* Wk = (const float*)d_in[3];
    const float* bk = (const float*)d_in[4];
    const float* Wv = (const float*)d_in[5];
    const float* bv = (const float*)d_in[6];
    const float* Wo = (const float*)d_in[7];
    const float* bo = (const float*)d_in[8];
    float* out = (float*)d_out;

    ln_stats_kernel<<<Bn * Cc, 256>>>(x);
    ln_norm_t_kernel<<<dim3(HW / 32, Cc / 32, Bn), dim3(32, 32)>>>(x);
    gemm_qkv_kernel<<<dim3(NP / 128, 6), 256>>>(Wq, bq, Wk, bk, Wv, bv);
    attn_kernel<<<NP / 8, 256>>>(bk, bv);
    gemm_o_kernel<<<dim3(NP / 128, 2), 256>>>(Wo, bo);
    out_transpose_kernel<<<dim3(Cc / 32, HW / 32, Bn), dim3(32, 32)>>>(out);
}

// round 4
// speedup vs baseline: 1.2274x; 1.2274x over previous
#include <cuda_runtime.h>
#include <cuda_bf16.h>
#include <mma.h>
#include <cstdint>

using namespace nvcuda;

// Problem constants
#define Bn   4
#define Cc   256
#define Hh   64
#define Ww   64
#define HW   4096
#define NP   16384
#define EPSV 1e-5f
#define QSCALE 0.0625f

// ---------------------------------------------------------------------------
// Scratch
// ---------------------------------------------------------------------------
__device__ float g_q[NP * Cc];
__device__ float g_k[NP * Cc];
__device__ float g_v[NP * Cc];
__device__ __nv_bfloat16 g_a_hi[NP * Cc];      // normalized input NHWC, bf16 hi
__device__ __nv_bfloat16 g_a_lo[NP * Cc];      // residual lo
__device__ __nv_bfloat16 g_c_hi[NP * Cc];      // attention ctx hi
__device__ __nv_bfloat16 g_c_lo[NP * Cc];      // ctx lo
__device__ __nv_bfloat16 g_w_hi[4 * Cc * Cc];  // Wq,Wk,Wv,Wo hi
__device__ __nv_bfloat16 g_w_lo[4 * Cc * Cc];  // lo
__device__ float g_mean[Bn * Cc];
__device__ float g_rstd[Bn * Cc];

// ---------------------------------------------------------------------------
// Kernel 1: per-(b,c)-plane mean / rstd
// ---------------------------------------------------------------------------
__global__ void ln_stats_kernel(const float* __restrict__ x) {
    int plane = blockIdx.x;
    const float* p = x + (size_t)plane * HW;
    float s = 0.f, ss = 0.f;
    for (int i = threadIdx.x; i < HW; i += 256) {
        float v = p[i];
        s += v; ss += v * v;
    }
    #pragma unroll
    for (int o = 16; o; o >>= 1) {
        s  += __shfl_xor_sync(0xffffffffu, s,  o);
        ss += __shfl_xor_sync(0xffffffffu, ss, o);
    }
    __shared__ float sh1[8], sh2[8];
    int wid = threadIdx.x >> 5, ln = threadIdx.x & 31;
    if (ln == 0) { sh1[wid] = s; sh2[wid] = ss; }
    __syncthreads();
    if (threadIdx.x < 8) {
        s = sh1[threadIdx.x]; ss = sh2[threadIdx.x];
        #pragma unroll
        for (int o = 4; o; o >>= 1) {
            s  += __shfl_xor_sync(0xffu, s,  o);
            ss += __shfl_xor_sync(0xffu, ss, o);
        }
        if (threadIdx.x == 0) {
            float mu  = s * (1.0f / HW);
            float var = ss * (1.0f / HW) - mu * mu;
            g_mean[plane] = mu;
            g_rstd[plane] = rsqrtf(var + EPSV);
        }
    }
}

// ---------------------------------------------------------------------------
// Kernel 2: normalize + transpose NCHW -> NHWC, emit bf16 hi/lo
// ---------------------------------------------------------------------------
__global__ void ln_norm_t_kernel(const float* __restrict__ x) {
    __shared__ float t[32][33];
    int b   = blockIdx.z;
    int c0  = blockIdx.y * 32;
    int hw0 = blockIdx.x * 32;
    int plane = b * Cc + c0 + threadIdx.y;
    float v = x[(size_t)plane * HW + hw0 + threadIdx.x];
    v = (v - g_mean[plane]) * g_rstd[plane];
    t[threadIdx.y][threadIdx.x] = v;
    __syncthreads();
    float o = t[threadIdx.x][threadIdx.y];
    size_t idx = ((size_t)(b * HW + hw0 + threadIdx.y)) * Cc + c0 + threadIdx.x;
    __nv_bfloat16 h = __float2bfloat16(o);
    g_a_hi[idx] = h;
    g_a_lo[idx] = __float2bfloat16(o - __bfloat162float(h));
}

// ---------------------------------------------------------------------------
// Kernel 3: weight hi/lo conversion
// ---------------------------------------------------------------------------
__global__ void wconv_kernel(const float* __restrict__ Wq, const float* __restrict__ Wk,
                             const float* __restrict__ Wv, const float* __restrict__ Wo) {
    int idx = blockIdx.x * 256 + threadIdx.x;
    int sel = idx >> 16, off = idx & 65535;
    const float* W = (sel == 0) ? Wq : (sel == 1) ? Wk : (sel == 2) ? Wv : Wo;
    float v = W[off];
    __nv_bfloat16 h = __float2bfloat16(v);
    g_w_hi[idx] = h;
    g_w_lo[idx] = __float2bfloat16(v - __bfloat162float(h));
}

// ---------------------------------------------------------------------------
// WMMA GEMM core.
// CTA computes C[128 x 128] = A'[128 x 768] * B'^T, where the effective
// K=768 is the split-bf16 expansion: pass0 Ah*Bh, pass1 Ah*Bl, pass2 Al*Bh.
// 256 threads, 8 warps, warp tile 32x64 (wm = wid&3, wn = wid>>2).
// Result left in smem Cs[128][132] (fp32).
// ---------------------------------------------------------------------------
#define LDA 72                  // bf16 elements per smem row (64 + 8 pad)
#define LDC 132                 // fp32 elements per Cs row
#define SM_AS 0
#define SM_BS (128 * LDA * 2)                 // 18432
#define SM_MAIN (SM_BS + 128 * LDA * 2)       // 36864
#define SM_BYTES (128 * LDC * 4)              // 67584 (Cs overlays As/Bs)

__device__ __forceinline__ void gemm_wmma_core(
    const __nv_bfloat16* __restrict__ Ah, const __nv_bfloat16* __restrict__ Al,
    const __nv_bfloat16* __restrict__ Wh, const __nv_bfloat16* __restrict__ Wl,
    int m0, int n0, char* smem)
{
    __nv_bfloat16* As = (__nv_bfloat16*)(smem + SM_AS);
    __nv_bfloat16* Bs = (__nv_bfloat16*)(smem + SM_BS);
    float* Cs = (float*)smem;

    const int tid = threadIdx.x;
    const int wid = tid >> 5;
    const int wm = wid & 3;       // 4 m-tiles of 32
    const int wn = wid >> 2;      // 2 n-tiles of 64

    wmma::fragment<wmma::accumulator, 16, 16, 16, float> acc[2][4];
    #pragma unroll
    for (int i = 0; i < 2; i++)
        #pragma unroll
        for (int j = 0; j < 4; j++) wmma::fill_fragment(acc[i][j], 0.0f);

    const __nv_bfloat16* Asrc[3] = {Ah, Ah, Al};
    const __nv_bfloat16* Bsrc[3] = {Wh, Wl, Wh};

    for (int ch = 0; ch < 12; ch++) {
        int pass = ch >> 2;
        int koff = (ch & 3) * 64;
        const __nv_bfloat16* A = Asrc[pass] + (size_t)m0 * Cc + koff;
        const __nv_bfloat16* B = Bsrc[pass] + (size_t)n0 * Cc + koff;
        __syncthreads();
        for (int i = tid; i < 1024; i += 256) {
            int r = i >> 3, c = (i & 7) << 3;       // 8 bf16 per uint4
            *(uint4*)(As + r * LDA + c) = *(const uint4*)(A + (size_t)r * Cc + c);
            *(uint4*)(Bs + r * LDA + c) = *(const uint4*)(B + (size_t)r * Cc + c);
        }
        __syncthreads();
        #pragma unroll
        for (int k16 = 0; k16 < 4; k16++) {
            wmma::fragment<wmma::matrix_a, 16, 16, 16, __nv_bfloat16, wmma::row_major> fa[2];
            wmma::fragment<wmma::matrix_b, 16, 16, 16, __nv_bfloat16, wmma::col_major> fb[4];
            #pragma unroll
            for (int i = 0; i < 2; i++)
                wmma::load_matrix_sync(fa[i], As + (wm * 32 + i * 16) * LDA + k16 * 16, LDA);
            #pragma unroll
            for (int j = 0; j < 4; j++)
                wmma::load_matrix_sync(fb[j], Bs + (wn * 64 + j * 16) * LDA + k16 * 16, LDA);
            #pragma unroll
            for (int i = 0; i < 2; i++)
                #pragma unroll
                for (int j = 0; j < 4; j++)
                    wmma::mma_sync(acc[i][j], fa[i], fb[j], acc[i][j]);
        }
    }
    __syncthreads();
    #pragma unroll
    for (int i = 0; i < 2; i++)
        #pragma unroll
        for (int j = 0; j < 4; j++)
            wmma::store_matrix_sync(Cs + (wm * 32 + i * 16) * LDC + wn * 64 + j * 16,
                                    acc[i][j], LDC, wmma::mem_row_major);
    __syncthreads();
}

// ---------------------------------------------------------------------------
// Kernel 4: fused QKV GEMM. grid (NP/128, 2, 3)
// ---------------------------------------------------------------------------
__global__ void __launch_bounds__(256) gemm_qkv_mma(
    const float* __restrict__ bq, const float* __restrict__ bk, const float* __restrict__ bv)
{
    extern __shared__ char smem[];
    const int m0 = blockIdx.x * 128;
    const int n0 = blockIdx.y * 128;
    const int sel = blockIdx.z;

    gemm_wmma_core(g_a_hi, g_a_lo,
                   g_w_hi + (size_t)sel * 65536, g_w_lo + (size_t)sel * 65536,
                   m0, n0, smem);

    const float* bias = (sel == 0) ? bq : (sel == 1) ? bk : bv;
    float* out        = (sel == 0) ? g_q : (sel == 1) ? g_k : g_v;
    const float scale = (sel == 0) ? QSCALE : 1.0f;
    float* Cs = (float*)smem;

    int half = threadIdx.x & 1, mrow = threadIdx.x >> 1;
    float* op = out + (size_t)(m0 + mrow) * Cc + n0;
    #pragma unroll
    for (int j = 0; j < 16; j++) {
        int n = half * 64 + j * 4;
        float4 v;
        v.x = (Cs[mrow * LDC + n + 0] + __ldg(bias + n0 + n + 0)) * scale;
        v.y = (Cs[mrow * LDC + n + 1] + __ldg(bias + n0 + n + 1)) * scale;
        v.z = (Cs[mrow * LDC + n + 2] + __ldg(bias + n0 + n + 2)) * scale;
        v.w = (Cs[mrow * LDC + n + 3] + __ldg(bias + n0 + n + 3)) * scale;
        *(float4*)(op + n) = v;
    }
}

// ---------------------------------------------------------------------------
// Kernel 5: 3x3 neighborhood attention (fp32 in, bf16 hi/lo ctx out)
// ---------------------------------------------------------------------------
__global__ void __launch_bounds__(256) attn_kernel(
    const float* __restrict__ bk, const float* __restrict__ bv)
{
    int warp = (blockIdx.x * blockDim.x + threadIdx.x) >> 5;
    int lane = threadIdx.x & 31;
    if (warp >= NP) return;
    int b  = warp >> 12;
    int hw = warp & 4095;
    int h = hw >> 6, w = hw & 63;
    int co = lane * 8;

    const float* qp = g_q + (size_t)warp * Cc;
    float4 q0 = *(const float4*)(qp + co);
    float4 q1 = *(const float4*)(qp + co + 4);

    float logits[9];
    #pragma unroll
    for (int n = 0; n < 9; n++) {
        int dh = n / 3 - 1, dw = n % 3 - 1;
        int hh = h + dh, ww = w + dw;
        bool ok = (hh >= 0) & (hh < Hh) & (ww >= 0) & (ww < Ww);
        const float* kp = ok ? (g_k + (size_t)((b << 12) + (hh << 6) + ww) * Cc) : bk;
        float4 k0 = *(const float4*)(kp + co);
        float4 k1 = *(const float4*)(kp + co + 4);
        float d = q0.x*k0.x + q0.y*k0.y + q0.z*k0.z + q0.w*k0.w
                + q1.x*k1.x + q1.y*k1.y + q1.z*k1.z + q1.w*k1.w;
        #pragma unroll
        for (int o = 16; o; o >>= 1) d += __shfl_xor_sync(0xffffffffu, d, o);
        logits[n] = d;
    }

    float mx = logits[0];
    #pragma unroll
    for (int n = 1; n < 9; n++) mx = fmaxf(mx, logits[n]);
    float e[9]; float sum = 0.f;
    #pragma unroll
    for (int n = 0; n < 9; n++) { e[n] = __expf(logits[n] - mx); sum += e[n]; }
    float inv = 1.0f / sum;

    float acc[8] = {0,0,0,0,0,0,0,0};
    #pragma unroll
    for (int n = 0; n < 9; n++) {
        int dh = n / 3 - 1, dw = n % 3 - 1;
        int hh = h + dh, ww = w + dw;
        bool ok = (hh >= 0) & (hh < Hh) & (ww >= 0) & (ww < Ww);
        const float* vp = ok ? (g_v + (size_t)((b << 12) + (hh << 6) + ww) * Cc) : bv;
        float a = e[n] * inv;
        float4 v0 = *(const float4*)(vp + co);
        float4 v1 = *(const float4*)(vp + co + 4);
        acc[0] = fmaf(a, v0.x, acc[0]); acc[1] = fmaf(a, v0.y, acc[1]);
        acc[2] = fmaf(a, v0.z, acc[2]); acc[3] = fmaf(a, v0.w, acc[3]);
        acc[4] = fmaf(a, v1.x, acc[4]); acc[5] = fmaf(a, v1.y, acc[5]);
        acc[6] = fmaf(a, v1.z, acc[6]); acc[7] = fmaf(a, v1.w, acc[7]);
    }

    uint32_t ph[4], pl[4];
    #pragma unroll
    for (int i = 0; i < 4; i++) {
        float a0 = acc[2*i], a1 = acc[2*i+1];
        __nv_bfloat162 h2 = __floats2bfloat162_rn(a0, a1);
        float h0 = __low2float(h2), h1 = __high2float(h2);
        __nv_bfloat162 l2 = __floats2bfloat162_rn(a0 - h0, a1 - h1);
        ph[i] = *reinterpret_cast<uint32_t*>(&h2);
        pl[i] = *reinterpret_cast<uint32_t*>(&l2);
    }
    size_t base = (size_t)warp * Cc + co;
    *(uint4*)(g_c_hi + base) = make_uint4(ph[0], ph[1], ph[2], ph[3]);
    *(uint4*)(g_c_lo + base) = make_uint4(pl[0], pl[1], pl[2], pl[3]);
}

// ---------------------------------------------------------------------------
// Kernel 6: output projection GEMM, epilogue writes NCHW directly.
// grid (NP/128, 2)
// ---------------------------------------------------------------------------
__global__ void __launch_bounds__(256) gemm_o_mma(
    const float* __restrict__ bo, float* __restrict__ out)
{
    extern __shared__ char smem[];
    const int m0 = blockIdx.x * 128;
    const int n0 = blockIdx.y * 128;

    gemm_wmma_core(g_c_hi, g_c_lo,
                   g_w_hi + (size_t)3 * 65536, g_w_lo + (size_t)3 * 65536,
                   m0, n0, smem);

    float* Cs = (float*)smem;
    const int wid = threadIdx.x >> 5, lane = threadIdx.x & 31;
    const int b   = m0 >> 12;
    const int hw0 = m0 & 4095;

    // warp handles columns n = wid, wid+8, ... ; lane covers 4 consecutive m
    for (int nn = wid; nn < 128; nn += 8) {
        int m = lane * 4;
        float bias = __ldg(bo + n0 + nn);
        float4 v;
        v.x = Cs[(m + 0) * LDC + nn] + bias;
        v.y = Cs[(m + 1) * LDC + nn] + bias;
        v.z = Cs[(m + 2) * LDC + nn] + bias;
        v.w = Cs[(m + 3) * LDC + nn] + bias;
        *(float4*)(out + ((size_t)(b * 256 + n0 + nn)) * HW + hw0 + m) = v;
    }
}

// ---------------------------------------------------------------------------
extern "C" void kernel_launch(void* const* d_in, const int* in_sizes, int n_in,
                              void* d_out, int out_size) {
    const float* x  = (const float*)d_in[0];
    const float* Wq = (const float*)d_in[1];
    const float* bq = (const float*)d_in[2];
    const float* Wk = (const float*)d_in[3];
    const float* bk = (const float*)d_in[4];
    const float* Wv = (const float*)d_in[5];
    const float* bv = (const float*)d_in[6];
    const float* Wo = (const float*)d_in[7];
    const float* bo = (const float*)d_in[8];
    float* out = (float*)d_out;

    static int configured = 0;
    if (!configured) {
        cudaFuncSetAttribute(gemm_qkv_mma, cudaFuncAttributeMaxDynamicSharedMemorySize, SM_BYTES);
        cudaFuncSetAttribute(gemm_o_mma,   cudaFuncAttributeMaxDynamicSharedMemorySize, SM_BYTES);
        configured = 1;
    }

    ln_stats_kernel<<<Bn * Cc, 256>>>(x);
    ln_norm_t_kernel<<<dim3(HW / 32, Cc / 32, Bn), dim3(32, 32)>>>(x);
    wconv_kernel<<<(4 * Cc * Cc) / 256, 256>>>(Wq, Wk, Wv, Wo);
    gemm_qkv_mma<<<dim3(NP / 128, 2, 3), 256, SM_BYTES>>>(bq, bk, bv);
    attn_kernel<<<NP / 8, 256>>>(bk, bv);
    gemm_o_mma<<<dim3(NP / 128, 2), 256, SM_BYTES>>>(bo, out);
}

// round 6
// speedup vs baseline: 1.4379x; 1.1715x over previous
#include <cuda_runtime.h>
#include <cuda_bf16.h>
#include <mma.h>
#include <cstdint>

using namespace nvcuda;

#define Bn   4
#define Cc   256
#define Hh   64
#define Ww   64
#define HW   4096
#define NP   16384
#define EPSV 1e-5f
#define QSCALE 0.0625f

// ---------------------------------------------------------------------------
// Scratch
// ---------------------------------------------------------------------------
__device__ float g_q[NP * Cc];
__device__ float g_k[NP * Cc];
__device__ float g_v[NP * Cc];
__device__ __nv_bfloat16 g_a_hi[NP * Cc];
__device__ __nv_bfloat16 g_a_lo[NP * Cc];
__device__ __nv_bfloat16 g_c_hi[NP * Cc];
__device__ __nv_bfloat16 g_c_lo[NP * Cc];
__device__ __nv_bfloat16 g_w_hi[4 * Cc * Cc];
__device__ __nv_bfloat16 g_w_lo[4 * Cc * Cc];
__device__ float g_mean[Bn * Cc];
__device__ float g_rstd[Bn * Cc];

// ---------------------------------------------------------------------------
__device__ __forceinline__ uint32_t smem_u32(const void* p) {
    uint32_t a;
    asm("{ .reg .u64 t; cvta.to.shared.u64 t, %1; cvt.u32.u64 %0, t; }" : "=r"(a) : "l"(p));
    return a;
}
__device__ __forceinline__ void cp16(uint32_t dst, const void* src) {
    asm volatile("cp.async.ca.shared.global [%0], [%1], 16;" :: "r"(dst), "l"(src));
}
#define CP_COMMIT() asm volatile("cp.async.commit_group;" ::: "memory")
#define CP_WAIT1()  asm volatile("cp.async.wait_group 1;" ::: "memory")
#define CP_WAIT0()  asm volatile("cp.async.wait_group 0;" ::: "memory")

// ---------------------------------------------------------------------------
// Kernel 1: per-(b,c)-plane mean / rstd
// ---------------------------------------------------------------------------
__global__ void ln_stats_kernel(const float* __restrict__ x) {
    int plane = blockIdx.x;
    const float* p = x + (size_t)plane * HW;
    float s = 0.f, ss = 0.f;
    for (int i = threadIdx.x; i < HW; i += 256) {
        float v = p[i];
        s += v; ss += v * v;
    }
    #pragma unroll
    for (int o = 16; o; o >>= 1) {
        s  += __shfl_xor_sync(0xffffffffu, s,  o);
        ss += __shfl_xor_sync(0xffffffffu, ss, o);
    }
    __shared__ float sh1[8], sh2[8];
    int wid = threadIdx.x >> 5, ln = threadIdx.x & 31;
    if (ln == 0) { sh1[wid] = s; sh2[wid] = ss; }
    __syncthreads();
    if (threadIdx.x < 8) {
        s = sh1[threadIdx.x]; ss = sh2[threadIdx.x];
        #pragma unroll
        for (int o = 4; o; o >>= 1) {
            s  += __shfl_xor_sync(0xffu, s,  o);
            ss += __shfl_xor_sync(0xffu, ss, o);
        }
        if (threadIdx.x == 0) {
            float mu  = s * (1.0f / HW);
            float var = ss * (1.0f / HW) - mu * mu;
            g_mean[plane] = mu;
            g_rstd[plane] = rsqrtf(var + EPSV);
        }
    }
}

// ---------------------------------------------------------------------------
// Kernel 2: normalize + transpose NCHW -> NHWC, emit bf16 hi/lo
// ---------------------------------------------------------------------------
__global__ void ln_norm_t_kernel(const float* __restrict__ x) {
    __shared__ float t[32][33];
    int b   = blockIdx.z;
    int c0  = blockIdx.y * 32;
    int hw0 = blockIdx.x * 32;
    int plane = b * Cc + c0 + threadIdx.y;
    float v = x[(size_t)plane * HW + hw0 + threadIdx.x];
    v = (v - g_mean[plane]) * g_rstd[plane];
    t[threadIdx.y][threadIdx.x] = v;
    __syncthreads();
    float o = t[threadIdx.x][threadIdx.y];
    size_t idx = ((size_t)(b * HW + hw0 + threadIdx.y)) * Cc + c0 + threadIdx.x;
    __nv_bfloat16 h = __float2bfloat16(o);
    g_a_hi[idx] = h;
    g_a_lo[idx] = __float2bfloat16(o - __bfloat162float(h));
}

// ---------------------------------------------------------------------------
// Kernel 3: weight hi/lo conversion
// ---------------------------------------------------------------------------
__global__ void wconv_kernel(const float* __restrict__ Wq, const float* __restrict__ Wk,
                             const float* __restrict__ Wv, const float* __restrict__ Wo) {
    int idx = blockIdx.x * 256 + threadIdx.x;
    int sel = idx >> 16, off = idx & 65535;
    const float* W = (sel == 0) ? Wq : (sel == 1) ? Wk : (sel == 2) ? Wv : Wo;
    float v = W[off];
    __nv_bfloat16 h = __float2bfloat16(v);
    g_w_hi[idx] = h;
    g_w_lo[idx] = __float2bfloat16(v - __bfloat162float(h));
}

// ---------------------------------------------------------------------------
// Pipelined WMMA GEMM core.
// C[128x128] = Ah*Bh^T + Ah*Bl^T + Al*Bh^T over K=256, in 8 chunks of K=32.
// cp.async double-buffered. Result left in smem Cs[128][132] fp32.
// ---------------------------------------------------------------------------
#define LDS_ELT 40                     // bf16 elements per stage row (32 + 8 pad), 80B
#define T_BYTES (128 * LDS_ELT * 2)    // 10240 per tile
#define STG_BYTES (4 * T_BYTES)        // 40960 per stage (Ah, Al, Bh, Bl)
#define LDC 132
#define SM_BYTES (2 * STG_BYTES)       // 81920 (Cs 67584 overlays)

__device__ __forceinline__ void gemm_core(
    const __nv_bfloat16* __restrict__ Ah, const __nv_bfloat16* __restrict__ Al,
    const __nv_bfloat16* __restrict__ Wh, const __nv_bfloat16* __restrict__ Wl,
    int m0, int n0, char* smem)
{
    const uint32_t sb = smem_u32(smem);
    const int tid = threadIdx.x;
    const int wid = tid >> 5;
    const int wm = wid & 3;            // 4 m-tiles of 32
    const int wn = wid >> 2;           // 2 n-tiles of 64

    const char* srcs[4] = {
        (const char*)(Ah + (size_t)m0 * Cc),
        (const char*)(Al + (size_t)m0 * Cc),
        (const char*)(Wh + (size_t)n0 * Cc),
        (const char*)(Wl + (size_t)n0 * Cc)
    };

    // per-thread fixed assignment: 8 cp.async of 16B each per chunk
    // idx = t*256+tid ; tile = idx>>9 ; r = (idx&511)>>2 ; seg = idx&3
    wmma::fragment<wmma::accumulator, 16, 16, 16, float> acc[2][4];
    #pragma unroll
    for (int i = 0; i < 2; i++)
        #pragma unroll
        for (int j = 0; j < 4; j++) wmma::fill_fragment(acc[i][j], 0.0f);

    auto load_chunk = [&](int ch, int buf) {
        uint32_t sbase = sb + buf * STG_BYTES;
        #pragma unroll
        for (int t = 0; t < 8; t++) {
            int idx  = t * 256 + tid;
            int tile = idx >> 9;
            int pos  = idx & 511;
            int r    = pos >> 2;
            int seg  = pos & 3;
            uint32_t dst = sbase + tile * T_BYTES + r * 80 + seg * 16;
            const char* src = srcs[tile] + (size_t)r * 512 + ch * 64 + seg * 16;
            cp16(dst, src);
        }
        CP_COMMIT();
    };

    load_chunk(0, 0);

    for (int ch = 0; ch < 8; ch++) {
        if (ch < 7) { load_chunk(ch + 1, (ch + 1) & 1); CP_WAIT1(); }
        else        { CP_WAIT0(); }
        __syncthreads();

        const __nv_bfloat16* Ash = (const __nv_bfloat16*)(smem + (ch & 1) * STG_BYTES);
        const __nv_bfloat16* Asl = (const __nv_bfloat16*)(smem + (ch & 1) * STG_BYTES + T_BYTES);
        const __nv_bfloat16* Bsh = (const __nv_bfloat16*)(smem + (ch & 1) * STG_BYTES + 2 * T_BYTES);
        const __nv_bfloat16* Bsl = (const __nv_bfloat16*)(smem + (ch & 1) * STG_BYTES + 3 * T_BYTES);

        #pragma unroll
        for (int k16 = 0; k16 < 2; k16++) {
            wmma::fragment<wmma::matrix_a, 16, 16, 16, __nv_bfloat16, wmma::row_major> fah[2], fal[2];
            wmma::fragment<wmma::matrix_b, 16, 16, 16, __nv_bfloat16, wmma::col_major> fbh[4], fbl[4];
            #pragma unroll
            for (int i = 0; i < 2; i++) {
                wmma::load_matrix_sync(fah[i], Ash + (wm * 32 + i * 16) * LDS_ELT + k16 * 16, LDS_ELT);
                wmma::load_matrix_sync(fal[i], Asl + (wm * 32 + i * 16) * LDS_ELT + k16 * 16, LDS_ELT);
            }
            #pragma unroll
            for (int j = 0; j < 4; j++) {
                wmma::load_matrix_sync(fbh[j], Bsh + (wn * 64 + j * 16) * LDS_ELT + k16 * 16, LDS_ELT);
                wmma::load_matrix_sync(fbl[j], Bsl + (wn * 64 + j * 16) * LDS_ELT + k16 * 16, LDS_ELT);
            }
            #pragma unroll
            for (int i = 0; i < 2; i++)
                #pragma unroll
                for (int j = 0; j < 4; j++) {
                    wmma::mma_sync(acc[i][j], fah[i], fbh[j], acc[i][j]);
                    wmma::mma_sync(acc[i][j], fah[i], fbl[j], acc[i][j]);
                    wmma::mma_sync(acc[i][j], fal[i], fbh[j], acc[i][j]);
                }
        }
        __syncthreads();
    }

    // dump accumulators to smem Cs (overlays stage buffers; all MMA done)
    float* Cs = (float*)smem;
    #pragma unroll
    for (int i = 0; i < 2; i++)
        #pragma unroll
        for (int j = 0; j < 4; j++)
            wmma::store_matrix_sync(Cs + (wm * 32 + i * 16) * LDC + wn * 64 + j * 16,
                                    acc[i][j], LDC, wmma::mem_row_major);
    __syncthreads();
}

// ---------------------------------------------------------------------------
// Kernel 4: fused QKV GEMM. grid (NP/128, 2, 3)
// ---------------------------------------------------------------------------
__global__ void __launch_bounds__(256) gemm_qkv_mma(
    const float* __restrict__ bq, const float* __restrict__ bk, const float* __restrict__ bv)
{
    extern __shared__ char smem[];
    const int m0 = blockIdx.x * 128;
    const int n0 = blockIdx.y * 128;
    const int sel = blockIdx.z;

    gemm_core(g_a_hi, g_a_lo,
              g_w_hi + (size_t)sel * 65536, g_w_lo + (size_t)sel * 65536,
              m0, n0, smem);

    const float* bias = (sel == 0) ? bq : (sel == 1) ? bk : bv;
    float* out        = (sel == 0) ? g_q : (sel == 1) ? g_k : g_v;
    const float scale = (sel == 0) ? QSCALE : 1.0f;
    float* Cs = (float*)smem;

    int half = threadIdx.x & 1, mrow = threadIdx.x >> 1;
    float* op = out + (size_t)(m0 + mrow) * Cc + n0;
    #pragma unroll
    for (int j = 0; j < 16; j++) {
        int n = half * 64 + j * 4;
        float4 v;
        v.x = (Cs[mrow * LDC + n + 0] + __ldg(bias + n0 + n + 0)) * scale;
        v.y = (Cs[mrow * LDC + n + 1] + __ldg(bias + n0 + n + 1)) * scale;
        v.z = (Cs[mrow * LDC + n + 2] + __ldg(bias + n0 + n + 2)) * scale;
        v.w = (Cs[mrow * LDC + n + 3] + __ldg(bias + n0 + n + 3)) * scale;
        *(float4*)(op + n) = v;
    }
}

// ---------------------------------------------------------------------------
// Kernel 5: 3x3 neighborhood attention
// ---------------------------------------------------------------------------
__global__ void __launch_bounds__(256) attn_kernel(
    const float* __restrict__ bk, const float* __restrict__ bv)
{
    int warp = (blockIdx.x * blockDim.x + threadIdx.x) >> 5;
    int lane = threadIdx.x & 31;
    if (warp >= NP) return;
    int b  = warp >> 12;
    int hw = warp & 4095;
    int h = hw >> 6, w = hw & 63;
    int co = lane * 8;

    const float* qp = g_q + (size_t)warp * Cc;
    float4 q0 = *(const float4*)(qp + co);
    float4 q1 = *(const float4*)(qp + co + 4);

    float logits[9];
    #pragma unroll
    for (int n = 0; n < 9; n++) {
        int dh = n / 3 - 1, dw = n % 3 - 1;
        int hh = h + dh, ww = w + dw;
        bool ok = (hh >= 0) & (hh < Hh) & (ww >= 0) & (ww < Ww);
        const float* kp = ok ? (g_k + (size_t)((b << 12) + (hh << 6) + ww) * Cc) : bk;
        float4 k0 = *(const float4*)(kp + co);
        float4 k1 = *(const float4*)(kp + co + 4);
        float d = q0.x*k0.x + q0.y*k0.y + q0.z*k0.z + q0.w*k0.w
                + q1.x*k1.x + q1.y*k1.y + q1.z*k1.z + q1.w*k1.w;
        #pragma unroll
        for (int o = 16; o; o >>= 1) d += __shfl_xor_sync(0xffffffffu, d, o);
        logits[n] = d;
    }

    float mx = logits[0];
    #pragma unroll
    for (int n = 1; n < 9; n++) mx = fmaxf(mx, logits[n]);
    float e[9]; float sum = 0.f;
    #pragma unroll
    for (int n = 0; n < 9; n++) { e[n] = __expf(logits[n] - mx); sum += e[n]; }
    float inv = 1.0f / sum;

    float acc[8] = {0,0,0,0,0,0,0,0};
    #pragma unroll
    for (int n = 0; n < 9; n++) {
        int dh = n / 3 - 1, dw = n % 3 - 1;
        int hh = h + dh, ww = w + dw;
        bool ok = (hh >= 0) & (hh < Hh) & (ww >= 0) & (ww < Ww);
        const float* vp = ok ? (g_v + (size_t)((b << 12) + (hh << 6) + ww) * Cc) : bv;
        float a = e[n] * inv;
        float4 v0 = *(const float4*)(vp + co);
        float4 v1 = *(const float4*)(vp + co + 4);
        acc[0] = fmaf(a, v0.x, acc[0]); acc[1] = fmaf(a, v0.y, acc[1]);
        acc[2] = fmaf(a, v0.z, acc[2]); acc[3] = fmaf(a, v0.w, acc[3]);
        acc[4] = fmaf(a, v1.x, acc[4]); acc[5] = fmaf(a, v1.y, acc[5]);
        acc[6] = fmaf(a, v1.z, acc[6]); acc[7] = fmaf(a, v1.w, acc[7]);
    }

    uint32_t ph[4], pl[4];
    #pragma unroll
    for (int i = 0; i < 4; i++) {
        float a0 = acc[2*i], a1 = acc[2*i+1];
        __nv_bfloat162 h2 = __floats2bfloat162_rn(a0, a1);
        float h0 = __low2float(h2), h1 = __high2float(h2);
        __nv_bfloat162 l2 = __floats2bfloat162_rn(a0 - h0, a1 - h1);
        ph[i] = *reinterpret_cast<uint32_t*>(&h2);
        pl[i] = *reinterpret_cast<uint32_t*>(&l2);
    }
    size_t base = (size_t)warp * Cc + co;
    *(uint4*)(g_c_hi + base) = make_uint4(ph[0], ph[1], ph[2], ph[3]);
    *(uint4*)(g_c_lo + base) = make_uint4(pl[0], pl[1], pl[2], pl[3]);
}

// ---------------------------------------------------------------------------
// Kernel 6: output projection GEMM, writes NCHW directly. grid (NP/128, 2)
// ---------------------------------------------------------------------------
__global__ void __launch_bounds__(256) gemm_o_mma(
    const float* __restrict__ bo, float* __restrict__ out)
{
    extern __shared__ char smem[];
    const int m0 = blockIdx.x * 128;
    const int n0 = blockIdx.y * 128;

    gemm_core(g_c_hi, g_c_lo,
              g_w_hi + (size_t)3 * 65536, g_w_lo + (size_t)3 * 65536,
              m0, n0, smem);

    float* Cs = (float*)smem;
    const int wid = threadIdx.x >> 5, lane = threadIdx.x & 31;
    const int b   = m0 >> 12;
    const int hw0 = m0 & 4095;

    for (int nn = wid; nn < 128; nn += 8) {
        int m = lane * 4;
        float bias = __ldg(bo + n0 + nn);
        float4 v;
        v.x = Cs[(m + 0) * LDC + nn] + bias;
        v.y = Cs[(m + 1) * LDC + nn] + bias;
        v.z = Cs[(m + 2) * LDC + nn] + bias;
        v.w = Cs[(m + 3) * LDC + nn] + bias;
        *(float4*)(out + ((size_t)(b * 256 + n0 + nn)) * HW + hw0 + m) = v;
    }
}

// ---------------------------------------------------------------------------
extern "C" void kernel_launch(void* const* d_in, const int* in_sizes, int n_in,
                              void* d_out, int out_size) {
    const float* x  = (const float*)d_in[0];
    const float* Wq = (const float*)d_in[1];
    const float* bq = (const float*)d_in[2];
    const float* Wk = (const float*)d_in[3];
    const float* bk = (const float*)d_in[4];
    const float* Wv = (const float*)d_in[5];
    const float* bv = (const float*)d_in[6];
    const float* Wo = (const float*)d_in[7];
    const float* bo = (const float*)d_in[8];
    float* out = (float*)d_out;

    static int configured = 0;
    if (!configured) {
        cudaFuncSetAttribute(gemm_qkv_mma, cudaFuncAttributeMaxDynamicSharedMemorySize, SM_BYTES);
        cudaFuncSetAttribute(gemm_o_mma,   cudaFuncAttributeMaxDynamicSharedMemorySize, SM_BYTES);
        configured = 1;
    }

    ln_stats_kernel<<<Bn * Cc, 256>>>(x);
    ln_norm_t_kernel<<<dim3(HW / 32, Cc / 32, Bn), dim3(32, 32)>>>(x);
    wconv_kernel<<<(4 * Cc * Cc) / 256, 256>>>(Wq, Wk, Wv, Wo);
    gemm_qkv_mma<<<dim3(NP / 128, 2, 3), 256, SM_BYTES>>>(bq, bk, bv);
    attn_kernel<<<NP / 8, 256>>>(bk, bv);
    gemm_o_mma<<<dim3(NP / 128, 2), 256, SM_BYTES>>>(bo, out);
}

// round 7
// speedup vs baseline: 1.6010x; 1.1134x over previous
#include <cuda_runtime.h>
#include <cuda_bf16.h>
#include <mma.h>
#include <cstdint>

using namespace nvcuda;

#define Bn   4
#define Cc   256
#define Hh   64
#define Ww   64
#define HW   4096
#define NP   16384
#define EPSV 1e-5f
#define QSCALE 0.0625f

// ---------------------------------------------------------------------------
// Scratch
// ---------------------------------------------------------------------------
__device__ float g_q[NP * Cc];
__device__ float g_k[NP * Cc];
__device__ float g_v[NP * Cc];
__device__ __nv_bfloat16 g_a_hi[NP * Cc];
__device__ __nv_bfloat16 g_a_lo[NP * Cc];
__device__ __nv_bfloat16 g_c_hi[NP * Cc];
__device__ __nv_bfloat16 g_c_lo[NP * Cc];
__device__ __nv_bfloat16 g_w_hi[4 * Cc * Cc];
__device__ __nv_bfloat16 g_w_lo[4 * Cc * Cc];
__device__ float g_mean[Bn * Cc];
__device__ float g_rstd[Bn * Cc];

// ---------------------------------------------------------------------------
__device__ __forceinline__ uint32_t smem_u32(const void* p) {
    uint32_t a;
    asm("{ .reg .u64 t; cvta.to.shared.u64 t, %1; cvt.u32.u64 %0, t; }" : "=r"(a) : "l"(p));
    return a;
}
__device__ __forceinline__ void cp16(uint32_t dst, const void* src) {
    asm volatile("cp.async.ca.shared.global [%0], [%1], 16;" :: "r"(dst), "l"(src));
}
#define CP_COMMIT() asm volatile("cp.async.commit_group;" ::: "memory")
#define CP_WAIT1()  asm volatile("cp.async.wait_group 1;" ::: "memory")
#define CP_WAIT0()  asm volatile("cp.async.wait_group 0;" ::: "memory")

// ---------------------------------------------------------------------------
// Kernel 1: per-(b,c)-plane mean / rstd
// ---------------------------------------------------------------------------
__global__ void ln_stats_kernel(const float* __restrict__ x) {
    int plane = blockIdx.x;
    const float* p = x + (size_t)plane * HW;
    float s = 0.f, ss = 0.f;
    for (int i = threadIdx.x; i < HW; i += 256) {
        float v = p[i];
        s += v; ss += v * v;
    }
    #pragma unroll
    for (int o = 16; o; o >>= 1) {
        s  += __shfl_xor_sync(0xffffffffu, s,  o);
        ss += __shfl_xor_sync(0xffffffffu, ss, o);
    }
    __shared__ float sh1[8], sh2[8];
    int wid = threadIdx.x >> 5, ln = threadIdx.x & 31;
    if (ln == 0) { sh1[wid] = s; sh2[wid] = ss; }
    __syncthreads();
    if (threadIdx.x < 8) {
        s = sh1[threadIdx.x]; ss = sh2[threadIdx.x];
        #pragma unroll
        for (int o = 4; o; o >>= 1) {
            s  += __shfl_xor_sync(0xffu, s,  o);
            ss += __shfl_xor_sync(0xffu, ss, o);
        }
        if (threadIdx.x == 0) {
            float mu  = s * (1.0f / HW);
            float var = ss * (1.0f / HW) - mu * mu;
            g_mean[plane] = mu;
            g_rstd[plane] = rsqrtf(var + EPSV);
        }
    }
}

// ---------------------------------------------------------------------------
// Kernel 2: normalize + transpose NCHW -> NHWC, emit bf16 hi/lo
// ---------------------------------------------------------------------------
__global__ void ln_norm_t_kernel(const float* __restrict__ x) {
    __shared__ float t[32][33];
    int b   = blockIdx.z;
    int c0  = blockIdx.y * 32;
    int hw0 = blockIdx.x * 32;
    int plane = b * Cc + c0 + threadIdx.y;
    float v = x[(size_t)plane * HW + hw0 + threadIdx.x];
    v = (v - g_mean[plane]) * g_rstd[plane];
    t[threadIdx.y][threadIdx.x] = v;
    __syncthreads();
    float o = t[threadIdx.x][threadIdx.y];
    size_t idx = ((size_t)(b * HW + hw0 + threadIdx.y)) * Cc + c0 + threadIdx.x;
    __nv_bfloat16 h = __float2bfloat16(o);
    g_a_hi[idx] = h;
    g_a_lo[idx] = __float2bfloat16(o - __bfloat162float(h));
}

// ---------------------------------------------------------------------------
// Kernel 3: weight hi/lo conversion
// ---------------------------------------------------------------------------
__global__ void wconv_kernel(const float* __restrict__ Wq, const float* __restrict__ Wk,
                             const float* __restrict__ Wv, const float* __restrict__ Wo) {
    int idx = blockIdx.x * 256 + threadIdx.x;
    int sel = idx >> 16, off = idx & 65535;
    const float* W = (sel == 0) ? Wq : (sel == 1) ? Wk : (sel == 2) ? Wv : Wo;
    float v = W[off];
    __nv_bfloat16 h = __float2bfloat16(v);
    g_w_hi[idx] = h;
    g_w_lo[idx] = __float2bfloat16(v - __bfloat162float(h));
}

// ---------------------------------------------------------------------------
// Pipelined WMMA GEMM core (register-lean inner loop: A frags hoisted,
// one B hi/lo pair live at a time).
// C[128x128] = Ah*Bh^T + Ah*Bl^T + Al*Bh^T over K=256, 8 chunks of 32.
// ---------------------------------------------------------------------------
#define LDS_ELT 40
#define T_BYTES (128 * LDS_ELT * 2)    // 10240
#define STG_BYTES (4 * T_BYTES)        // 40960
#define LDC 132
#define SM_BYTES (2 * STG_BYTES)       // 81920

__device__ __forceinline__ void gemm_core(
    const __nv_bfloat16* __restrict__ Ah, const __nv_bfloat16* __restrict__ Al,
    const __nv_bfloat16* __restrict__ Wh, const __nv_bfloat16* __restrict__ Wl,
    int m0, int n0, char* smem)
{
    const uint32_t sb = smem_u32(smem);
    const int tid = threadIdx.x;
    const int wid = tid >> 5;
    const int wm = wid & 3;
    const int wn = wid >> 2;

    const char* srcs[4] = {
        (const char*)(Ah + (size_t)m0 * Cc),
        (const char*)(Al + (size_t)m0 * Cc),
        (const char*)(Wh + (size_t)n0 * Cc),
        (const char*)(Wl + (size_t)n0 * Cc)
    };

    wmma::fragment<wmma::accumulator, 16, 16, 16, float> acc[2][4];
    #pragma unroll
    for (int i = 0; i < 2; i++)
        #pragma unroll
        for (int j = 0; j < 4; j++) wmma::fill_fragment(acc[i][j], 0.0f);

    auto load_chunk = [&](int ch, int buf) {
        uint32_t sbase = sb + buf * STG_BYTES;
        #pragma unroll
        for (int t = 0; t < 8; t++) {
            int idx  = t * 256 + tid;
            int tile = idx >> 9;
            int pos  = idx & 511;
            int r    = pos >> 2;
            int seg  = pos & 3;
            uint32_t dst = sbase + tile * T_BYTES + r * 80 + seg * 16;
            const char* src = srcs[tile] + (size_t)r * 512 + ch * 64 + seg * 16;
            cp16(dst, src);
        }
        CP_COMMIT();
    };

    load_chunk(0, 0);

    for (int ch = 0; ch < 8; ch++) {
        if (ch < 7) { load_chunk(ch + 1, (ch + 1) & 1); CP_WAIT1(); }
        else        { CP_WAIT0(); }
        __syncthreads();

        const __nv_bfloat16* Ash = (const __nv_bfloat16*)(smem + (ch & 1) * STG_BYTES);
        const __nv_bfloat16* Asl = (const __nv_bfloat16*)(smem + (ch & 1) * STG_BYTES + T_BYTES);
        const __nv_bfloat16* Bsh = (const __nv_bfloat16*)(smem + (ch & 1) * STG_BYTES + 2 * T_BYTES);
        const __nv_bfloat16* Bsl = (const __nv_bfloat16*)(smem + (ch & 1) * STG_BYTES + 3 * T_BYTES);

        #pragma unroll
        for (int k16 = 0; k16 < 2; k16++) {
            wmma::fragment<wmma::matrix_a, 16, 16, 16, __nv_bfloat16, wmma::row_major> fah[2], fal[2];
            #pragma unroll
            for (int i = 0; i < 2; i++) {
                wmma::load_matrix_sync(fah[i], Ash + (wm * 32 + i * 16) * LDS_ELT + k16 * 16, LDS_ELT);
                wmma::load_matrix_sync(fal[i], Asl + (wm * 32 + i * 16) * LDS_ELT + k16 * 16, LDS_ELT);
            }
            #pragma unroll
            for (int j = 0; j < 4; j++) {
                wmma::fragment<wmma::matrix_b, 16, 16, 16, __nv_bfloat16, wmma::col_major> fbh, fbl;
                wmma::load_matrix_sync(fbh, Bsh + (wn * 64 + j * 16) * LDS_ELT + k16 * 16, LDS_ELT);
                wmma::load_matrix_sync(fbl, Bsl + (wn * 64 + j * 16) * LDS_ELT + k16 * 16, LDS_ELT);
                #pragma unroll
                for (int i = 0; i < 2; i++) {
                    wmma::mma_sync(acc[i][j], fah[i], fbh, acc[i][j]);
                    wmma::mma_sync(acc[i][j], fah[i], fbl, acc[i][j]);
                    wmma::mma_sync(acc[i][j], fal[i], fbh, acc[i][j]);
                }
            }
        }
        __syncthreads();
    }

    float* Cs = (float*)smem;
    #pragma unroll
    for (int i = 0; i < 2; i++)
        #pragma unroll
        for (int j = 0; j < 4; j++)
            wmma::store_matrix_sync(Cs + (wm * 32 + i * 16) * LDC + wn * 64 + j * 16,
                                    acc[i][j], LDC, wmma::mem_row_major);
    __syncthreads();
}

// ---------------------------------------------------------------------------
// Kernel 4: fused QKV GEMM. grid (NP/128, 2, 3)
// ---------------------------------------------------------------------------
__global__ void __launch_bounds__(256, 2) gemm_qkv_mma(
    const float* __restrict__ bq, const float* __restrict__ bk, const float* __restrict__ bv)
{
    extern __shared__ char smem[];
    const int m0 = blockIdx.x * 128;
    const int n0 = blockIdx.y * 128;
    const int sel = blockIdx.z;

    gemm_core(g_a_hi, g_a_lo,
              g_w_hi + (size_t)sel * 65536, g_w_lo + (size_t)sel * 65536,
              m0, n0, smem);

    const float* bias = (sel == 0) ? bq : (sel == 1) ? bk : bv;
    float* out        = (sel == 0) ? g_q : (sel == 1) ? g_k : g_v;
    const float scale = (sel == 0) ? QSCALE : 1.0f;
    float* Cs = (float*)smem;

    int half = threadIdx.x & 1, mrow = threadIdx.x >> 1;
    float* op = out + (size_t)(m0 + mrow) * Cc + n0;
    #pragma unroll
    for (int j = 0; j < 16; j++) {
        int n = half * 64 + j * 4;
        float4 v;
        v.x = (Cs[mrow * LDC + n + 0] + __ldg(bias + n0 + n + 0)) * scale;
        v.y = (Cs[mrow * LDC + n + 1] + __ldg(bias + n0 + n + 1)) * scale;
        v.z = (Cs[mrow * LDC + n + 2] + __ldg(bias + n0 + n + 2)) * scale;
        v.w = (Cs[mrow * LDC + n + 3] + __ldg(bias + n0 + n + 3)) * scale;
        *(float4*)(op + n) = v;
    }
}

// ---------------------------------------------------------------------------
// Kernel 5: 3x3 neighborhood attention
// ---------------------------------------------------------------------------
__global__ void __launch_bounds__(256) attn_kernel(
    const float* __restrict__ bk, const float* __restrict__ bv)
{
    int warp = (blockIdx.x * blockDim.x + threadIdx.x) >> 5;
    int lane = threadIdx.x & 31;
    if (warp >= NP) return;
    int b  = warp >> 12;
    int hw = warp & 4095;
    int h = hw >> 6, w = hw & 63;
    int co = lane * 8;

    const float* qp = g_q + (size_t)warp * Cc;
    float4 q0 = *(const float4*)(qp + co);
    float4 q1 = *(const float4*)(qp + co + 4);

    float logits[9];
    #pragma unroll
    for (int n = 0; n < 9; n++) {
        int dh = n / 3 - 1, dw = n % 3 - 1;
        int hh = h + dh, ww = w + dw;
        bool ok = (hh >= 0) & (hh < Hh) & (ww >= 0) & (ww < Ww);
        const float* kp = ok ? (g_k + (size_t)((b << 12) + (hh << 6) + ww) * Cc) : bk;
        float4 k0 = *(const float4*)(kp + co);
        float4 k1 = *(const float4*)(kp + co + 4);
        float d = q0.x*k0.x + q0.y*k0.y + q0.z*k0.z + q0.w*k0.w
                + q1.x*k1.x + q1.y*k1.y + q1.z*k1.z + q1.w*k1.w;
        #pragma unroll
        for (int o = 16; o; o >>= 1) d += __shfl_xor_sync(0xffffffffu, d, o);
        logits[n] = d;
    }

    float mx = logits[0];
    #pragma unroll
    for (int n = 1; n < 9; n++) mx = fmaxf(mx, logits[n]);
    float e[9]; float sum = 0.f;
    #pragma unroll
    for (int n = 0; n < 9; n++) { e[n] = __expf(logits[n] - mx); sum += e[n]; }
    float inv = 1.0f / sum;

    float acc[8] = {0,0,0,0,0,0,0,0};
    #pragma unroll
    for (int n = 0; n < 9; n++) {
        int dh = n / 3 - 1, dw = n % 3 - 1;
        int hh = h + dh, ww = w + dw;
        bool ok = (hh >= 0) & (hh < Hh) & (ww >= 0) & (ww < Ww);
        const float* vp = ok ? (g_v + (size_t)((b << 12) + (hh << 6) + ww) * Cc) : bv;
        float a = e[n] * inv;
        float4 v0 = *(const float4*)(vp + co);
        float4 v1 = *(const float4*)(vp + co + 4);
        acc[0] = fmaf(a, v0.x, acc[0]); acc[1] = fmaf(a, v0.y, acc[1]);
        acc[2] = fmaf(a, v0.z, acc[2]); acc[3] = fmaf(a, v0.w, acc[3]);
        acc[4] = fmaf(a, v1.x, acc[4]); acc[5] = fmaf(a, v1.y, acc[5]);
        acc[6] = fmaf(a, v1.z, acc[6]); acc[7] = fmaf(a, v1.w, acc[7]);
    }

    uint32_t ph[4], pl[4];
    #pragma unroll
    for (int i = 0; i < 4; i++) {
        float a0 = acc[2*i], a1 = acc[2*i+1];
        __nv_bfloat162 h2 = __floats2bfloat162_rn(a0, a1);
        float h0 = __low2float(h2), h1 = __high2float(h2);
        __nv_bfloat162 l2 = __floats2bfloat162_rn(a0 - h0, a1 - h1);
        ph[i] = *reinterpret_cast<uint32_t*>(&h2);
        pl[i] = *reinterpret_cast<uint32_t*>(&l2);
    }
    size_t base = (size_t)warp * Cc + co;
    *(uint4*)(g_c_hi + base) = make_uint4(ph[0], ph[1], ph[2], ph[3]);
    *(uint4*)(g_c_lo + base) = make_uint4(pl[0], pl[1], pl[2], pl[3]);
}

// ---------------------------------------------------------------------------
// Kernel 6: output projection GEMM, writes NCHW directly. grid (NP/128, 2)
// ---------------------------------------------------------------------------
__global__ void __launch_bounds__(256, 2) gemm_o_mma(
    const float* __restrict__ bo, float* __restrict__ out)
{
    extern __shared__ char smem[];
    const int m0 = blockIdx.x * 128;
    const int n0 = blockIdx.y * 128;

    gemm_core(g_c_hi, g_c_lo,
              g_w_hi + (size_t)3 * 65536, g_w_lo + (size_t)3 * 65536,
              m0, n0, smem);

    float* Cs = (float*)smem;
    const int wid = threadIdx.x >> 5, lane = threadIdx.x & 31;
    const int b   = m0 >> 12;
    const int hw0 = m0 & 4095;

    for (int nn = wid; nn < 128; nn += 8) {
        int m = lane * 4;
        float bias = __ldg(bo + n0 + nn);
        float4 v;
        v.x = Cs[(m + 0) * LDC + nn] + bias;
        v.y = Cs[(m + 1) * LDC + nn] + bias;
        v.z = Cs[(m + 2) * LDC + nn] + bias;
        v.w = Cs[(m + 3) * LDC + nn] + bias;
        *(float4*)(out + ((size_t)(b * 256 + n0 + nn)) * HW + hw0 + m) = v;
    }
}

// ---------------------------------------------------------------------------
extern "C" void kernel_launch(void* const* d_in, const int* in_sizes, int n_in,
                              void* d_out, int out_size) {
    const float* x  = (const float*)d_in[0];
    const float* Wq = (const float*)d_in[1];
    const float* bq = (const float*)d_in[2];
    const float* Wk = (const float*)d_in[3];
    const float* bk = (const float*)d_in[4];
    const float* Wv = (const float*)d_in[5];
    const float* bv = (const float*)d_in[6];
    const float* Wo = (const float*)d_in[7];
    const float* bo = (const float*)d_in[8];
    float* out = (float*)d_out;

    static int configured = 0;
    if (!configured) {
        cudaFuncSetAttribute(gemm_qkv_mma, cudaFuncAttributeMaxDynamicSharedMemorySize, SM_BYTES);
        cudaFuncSetAttribute(gemm_o_mma,   cudaFuncAttributeMaxDynamicSharedMemorySize, SM_BYTES);
        configured = 1;
    }

    ln_stats_kernel<<<Bn * Cc, 256>>>(x);
    ln_norm_t_kernel<<<dim3(HW / 32, Cc / 32, Bn), dim3(32, 32)>>>(x);
    wconv_kernel<<<(4 * Cc * Cc) / 256, 256>>>(Wq, Wk, Wv, Wo);
    gemm_qkv_mma<<<dim3(NP / 128, 2, 3), 256, SM_BYTES>>>(bq, bk, bv);
    attn_kernel<<<NP / 8, 256>>>(bk, bv);
    gemm_o_mma<<<dim3(NP / 128, 2), 256, SM_BYTES>>>(bo, out);
}